// round 1
// baseline (speedup 1.0000x reference)
#include <cuda_runtime.h>
#include <cstdint>

#define BB 4
#define NN 576
#define DM 512
#define DI 1024
#define DS 16
#define DTR 32
#define MT (BB*NN)   // 2304 tokens

// ---------------- workspace (static device memory; no runtime alloc) ----------------
// float counts
#define SZ_XN   (MT*DM)
#define SZ_XZ   (MT*2*DI)
#define SZ_U    (MT*DI)
#define SZ_XD   (MT*64)
#define SZ_DT   (MT*DI)
#define SZ_Y    (MT*DI)
#define SZ_CAT  (MT*2*DM)
#define SZ_X1   (MT*DM)
#define SZ_XN2  (MT*DM)
#define SZ_HFF  (MT*4*DM)

#define OFF_XN   0
#define OFF_XZ0  (OFF_XN + SZ_XN)
#define OFF_XZ1  (OFF_XZ0 + SZ_XZ)
#define OFF_U0   (OFF_XZ1 + SZ_XZ)
#define OFF_U1   (OFF_U0 + SZ_U)
#define OFF_XD0  (OFF_U1 + SZ_U)
#define OFF_XD1  (OFF_XD0 + SZ_XD)
#define OFF_DT0  (OFF_XD1 + SZ_XD)
#define OFF_DT1  (OFF_DT0 + SZ_DT)
#define OFF_Y0   (OFF_DT1 + SZ_DT)
#define OFF_Y1   (OFF_Y0 + SZ_Y)
#define OFF_CAT  (OFF_Y1 + SZ_Y)
#define OFF_X1   (OFF_CAT + SZ_CAT)
#define OFF_XN2  (OFF_X1 + SZ_X1)
#define OFF_HFF  (OFF_XN2 + SZ_XN2)
#define WS_TOTAL (OFF_HFF + SZ_HFF)

__device__ float g_ws[WS_TOTAL];

// ---------------- helpers ----------------
__device__ __forceinline__ float sigmoidf_(float x) { return 1.f / (1.f + __expf(-x)); }
__device__ __forceinline__ float softplusf_(float x) {
    return fmaxf(x, 0.f) + log1pf(__expf(-fabsf(x)));
}
__device__ __forceinline__ float gelu_tanh(float x) {
    float x3 = x * x * x;
    return 0.5f * x * (1.f + tanhf(0.7978845608028654f * (x + 0.044715f * x3)));
}

// ---------------- LayerNorm: one block per row ----------------
__global__ void ln_kernel(const float* __restrict__ x, const float* __restrict__ g,
                          const float* __restrict__ b, float* __restrict__ out) {
    int row = blockIdx.x;
    int t = threadIdx.x;              // 256 threads
    const float* xr = x + row * DM;
    float v0 = xr[t], v1 = xr[t + 256];
    float s = v0 + v1, q = v0 * v0 + v1 * v1;
    #pragma unroll
    for (int o = 16; o; o >>= 1) {
        s += __shfl_xor_sync(0xffffffffu, s, o);
        q += __shfl_xor_sync(0xffffffffu, q, o);
    }
    __shared__ float ss[8], qq[8];
    int w = t >> 5;
    if ((t & 31) == 0) { ss[w] = s; qq[w] = q; }
    __syncthreads();
    s = 0.f; q = 0.f;
    #pragma unroll
    for (int i = 0; i < 8; i++) { s += ss[i]; q += qq[i]; }
    float mean = s * (1.f / DM);
    float var = q * (1.f / DM) - mean * mean;
    float inv = rsqrtf(var + 1e-5f);
    out[row * DM + t]       = (v0 - mean) * inv * g[t] + b[t];
    out[row * DM + t + 256] = (v1 - mean) * inv * g[t + 256] + b[t + 256];
}

// ---------------- Generic SIMT fp32 GEMM: C = A(MxK) * W(NxK)^T (+epilogue) ----------------
// EPI: 0 none, 1 bias+softplus, 2 bias+residual, 3 bias+gelu
template <int EPI>
__global__ void __launch_bounds__(256, 2) gemm_kernel(
    const float* __restrict__ A, int lda,
    const float* __restrict__ W,
    const float* __restrict__ bias,
    const float* __restrict__ resid,
    float* __restrict__ C, int ldc, int coff, int K)
{
    __shared__ float As[16][64];
    __shared__ float Bs[16][64];
    const int m0 = blockIdx.x * 64;
    const int n0 = blockIdx.y * 64;
    const int tid = threadIdx.x;
    const int lr = tid >> 2;          // 0..63
    const int lc = (tid & 3) << 2;    // 0,4,8,12
    const int tx = tid & 15, ty = tid >> 4;

    float acc[4][4];
    #pragma unroll
    for (int i = 0; i < 4; i++)
        #pragma unroll
        for (int j = 0; j < 4; j++) acc[i][j] = 0.f;

    const float* Ap = A + (size_t)(m0 + lr) * lda + lc;
    const float* Wp = W + (size_t)(n0 + lr) * K + lc;

    for (int k0 = 0; k0 < K; k0 += 16) {
        float4 av = *(const float4*)(Ap + k0);
        float4 wv = *(const float4*)(Wp + k0);
        __syncthreads();
        As[lc + 0][lr] = av.x; As[lc + 1][lr] = av.y;
        As[lc + 2][lr] = av.z; As[lc + 3][lr] = av.w;
        Bs[lc + 0][lr] = wv.x; Bs[lc + 1][lr] = wv.y;
        Bs[lc + 2][lr] = wv.z; Bs[lc + 3][lr] = wv.w;
        __syncthreads();
        #pragma unroll
        for (int k = 0; k < 16; k++) {
            float4 a4 = *(const float4*)&As[k][ty << 2];
            float4 b4 = *(const float4*)&Bs[k][tx << 2];
            float ar[4] = {a4.x, a4.y, a4.z, a4.w};
            float br[4] = {b4.x, b4.y, b4.z, b4.w};
            #pragma unroll
            for (int i = 0; i < 4; i++)
                #pragma unroll
                for (int j = 0; j < 4; j++) acc[i][j] += ar[i] * br[j];
        }
    }

    #pragma unroll
    for (int i = 0; i < 4; i++) {
        int r = m0 + (ty << 2) + i;
        #pragma unroll
        for (int j = 0; j < 4; j++) {
            int n = n0 + (tx << 2) + j;
            float v = acc[i][j];
            if (EPI == 1) v = softplusf_(v + bias[n]);
            else if (EPI == 2) v = v + bias[n] + resid[(size_t)r * ldc + n];
            else if (EPI == 3) v = gelu_tanh(v + bias[n]);
            C[(size_t)r * ldc + coff + n] = v;
        }
    }
}

// ---------------- depthwise causal conv (dir 0) / anti-causal (dir 1) + SiLU ----------------
__global__ void conv_kernel(const float* __restrict__ xz, const float* __restrict__ w,
                            const float* __restrict__ cb, float* __restrict__ u, int dir)
{
    int i = blockIdx.x * 256 + threadIdx.x;
    if (i >= MT * DI) return;
    int c = i % DI;
    int row = i / DI;
    int n = row % NN, b = row / NN;
    float acc = cb[c];
    #pragma unroll
    for (int k = 0; k < 4; k++) {
        int nn = dir ? (n + 3 - k) : (n - 3 + k);
        if (nn >= 0 && nn < NN)
            acc += xz[(size_t)(b * NN + nn) * 2 * DI + c] * w[c * 4 + k];
    }
    u[i] = acc * sigmoidf_(acc);
}

// ---------------- selective scan, both directions in one launch ----------------
// grid: (B * DI/64, 2); block: 512 threads; each thread owns 2 (channel,state) pairs.
#define PF 6
__global__ void __launch_bounds__(512, 1) scan_kernel(
    const float* __restrict__ u0p, const float* __restrict__ u1p,
    const float* __restrict__ dt0p, const float* __restrict__ dt1p,
    const float* __restrict__ xd0p, const float* __restrict__ xd1p,
    const float* __restrict__ xz0p, const float* __restrict__ xz1p,
    const float* __restrict__ Al0, const float* __restrict__ Al1,
    const float* __restrict__ D0p, const float* __restrict__ D1p,
    float* __restrict__ y0p, float* __restrict__ y1p)
{
    const int dir = blockIdx.y;
    const float* up   = dir ? u1p  : u0p;
    const float* dtp  = dir ? dt1p : dt0p;
    const float* xdp  = dir ? xd1p : xd0p;
    const float* xzp  = dir ? xz1p : xz0p;
    const float* Alog = dir ? Al1  : Al0;
    const float* Dp   = dir ? D1p  : D0p;
    float* yp         = dir ? y1p  : y0p;

    __shared__ __align__(16) float sm[PF][224];
    const int bi = blockIdx.x >> 4;          // batch
    const int cb = (blockIdx.x & 15) << 6;   // channel base
    const int tid = threadIdx.x;
    const int s = tid & 15;
    const int cl0 = tid >> 4;                // 0..31
    const int c0 = cb + cl0, c1 = c0 + 32;

    const float A0 = -__expf(Alog[c0 * DS + s]);
    const float A1 = -__expf(Alog[c1 * DS + s]);
    const float Dc0 = Dp[c0], Dc1 = Dp[c1];
    float h0 = 0.f, h1 = 0.f;

    auto issue = [&](int stage, int n) {
        if (tid < 56) {
            int row = bi * NN + n;
            const float* src;
            int off;
            if (tid < 16)      { src = dtp + (size_t)row * DI + cb + tid * 4;               off = tid * 4; }
            else if (tid < 32) { src = up  + (size_t)row * DI + cb + (tid - 16) * 4;        off = 64 + (tid - 16) * 4; }
            else if (tid < 48) { src = xzp + (size_t)row * 2 * DI + DI + cb + (tid - 32) * 4; off = 128 + (tid - 32) * 4; }
            else if (tid < 52) { src = xdp + (size_t)row * 64 + 32 + (tid - 48) * 4;        off = 192 + (tid - 48) * 4; }
            else               { src = xdp + (size_t)row * 64 + 48 + (tid - 52) * 4;        off = 208 + (tid - 52) * 4; }
            uint32_t d = (uint32_t)__cvta_generic_to_shared(&sm[stage][off]);
            asm volatile("cp.async.ca.shared.global [%0], [%1], 16;\n" :: "r"(d), "l"(src));
        }
    };
    #define NIDX(st) (dir ? (NN - 1 - (st)) : (st))

    issue(0, NIDX(0)); asm volatile("cp.async.commit_group;");
    issue(1, NIDX(1)); asm volatile("cp.async.commit_group;");
    issue(2, NIDX(2)); asm volatile("cp.async.commit_group;");

    for (int step = 0; step < NN; step++) {
        if (step + 3 < NN) issue((step + 3) % PF, NIDX(step + 3));
        asm volatile("cp.async.commit_group;");
        asm volatile("cp.async.wait_group 3;");
        __syncthreads();
        const float* S = sm[step % PF];
        float dt0 = S[cl0],      dt1 = S[32 + cl0];
        float u0v = S[64 + cl0], u1v = S[96 + cl0];
        float Bv = S[192 + s],   Cv = S[208 + s];
        h0 = __expf(dt0 * A0) * h0 + dt0 * Bv * u0v;
        h1 = __expf(dt1 * A1) * h1 + dt1 * Bv * u1v;
        float y0 = h0 * Cv, y1 = h1 * Cv;
        #pragma unroll
        for (int o = 8; o; o >>= 1) {
            y0 += __shfl_xor_sync(0xffffffffu, y0, o);
            y1 += __shfl_xor_sync(0xffffffffu, y1, o);
        }
        if (s == 0) {
            int row = bi * NN + NIDX(step);
            float z0 = S[128 + cl0], z1 = S[160 + cl0];
            yp[(size_t)row * DI + c0] = (y0 + u0v * Dc0) * (z0 * sigmoidf_(z0));
            yp[(size_t)row * DI + c1] = (y1 + u1v * Dc1) * (z1 * sigmoidf_(z1));
        }
    }
    #undef NIDX
}

// ---------------- launch ----------------
extern "C" void kernel_launch(void* const* d_in, const int* in_sizes, int n_in,
                              void* d_out, int out_size) {
    const float* x  = (const float*)d_in[0];
    const float* g1 = (const float*)d_in[1];
    const float* b1 = (const float*)d_in[2];
    const float* g2 = (const float*)d_in[3];
    const float* b2 = (const float*)d_in[4];

    int base_f, base_r, base_m;
    if (in_sizes[5] == DM * 2 * DM) {        // merge_W (512*1024) => dict order
        base_m = 5; base_f = 11; base_r = 20;
    } else {                                  // f_Win (2048*512) => signature order
        base_f = 5; base_r = 14; base_m = 23;
    }
    const float *Win[2], *convw[2], *convb[2], *Wx[2], *Wdt[2], *bdt[2], *Alog[2], *Dp[2], *Wout[2];
    int bases[2] = {base_f, base_r};
    for (int d = 0; d < 2; d++) {
        int bs = bases[d];
        Win[d]   = (const float*)d_in[bs + 0];
        convw[d] = (const float*)d_in[bs + 1];
        convb[d] = (const float*)d_in[bs + 2];
        Wx[d]    = (const float*)d_in[bs + 3];
        Wdt[d]   = (const float*)d_in[bs + 4];
        bdt[d]   = (const float*)d_in[bs + 5];
        Alog[d]  = (const float*)d_in[bs + 6];
        Dp[d]    = (const float*)d_in[bs + 7];
        Wout[d]  = (const float*)d_in[bs + 8];
    }
    const float* merge_W = (const float*)d_in[base_m + 0];
    const float* merge_b = (const float*)d_in[base_m + 1];
    const float* ffn_W1  = (const float*)d_in[base_m + 2];
    const float* ffn_b1  = (const float*)d_in[base_m + 3];
    const float* ffn_W2  = (const float*)d_in[base_m + 4];
    const float* ffn_b2  = (const float*)d_in[base_m + 5];

    float* ws = nullptr;
    cudaGetSymbolAddress((void**)&ws, g_ws);
    float* xn  = ws + OFF_XN;
    float* xz[2]  = {ws + OFF_XZ0, ws + OFF_XZ1};
    float* u[2]   = {ws + OFF_U0,  ws + OFF_U1};
    float* xd[2]  = {ws + OFF_XD0, ws + OFF_XD1};
    float* dt[2]  = {ws + OFF_DT0, ws + OFF_DT1};
    float* y[2]   = {ws + OFF_Y0,  ws + OFF_Y1};
    float* cat = ws + OFF_CAT;
    float* x1  = ws + OFF_X1;
    float* xn2 = ws + OFF_XN2;
    float* hff = ws + OFF_HFF;

    const int MB = MT / 64;  // 36

    ln_kernel<<<MT, 256>>>(x, g1, b1, xn);

    for (int d = 0; d < 2; d++) {
        gemm_kernel<0><<<dim3(MB, 2 * DI / 64), 256>>>(xn, DM, Win[d], nullptr, nullptr,
                                                       xz[d], 2 * DI, 0, DM);
        conv_kernel<<<(MT * DI + 255) / 256, 256>>>(xz[d], convw[d], convb[d], u[d], d);
        gemm_kernel<0><<<dim3(MB, 1), 256>>>(u[d], DI, Wx[d], nullptr, nullptr,
                                             xd[d], 64, 0, DI);
        gemm_kernel<1><<<dim3(MB, DI / 64), 256>>>(xd[d], 64, Wdt[d], bdt[d], nullptr,
                                                   dt[d], DI, 0, DTR);
    }

    scan_kernel<<<dim3(BB * (DI / 64), 2), 512>>>(
        u[0], u[1], dt[0], dt[1], xd[0], xd[1], xz[0], xz[1],
        Alog[0], Alog[1], Dp[0], Dp[1], y[0], y[1]);

    for (int d = 0; d < 2; d++) {
        gemm_kernel<0><<<dim3(MB, DM / 64), 256>>>(y[d], DI, Wout[d], nullptr, nullptr,
                                                   cat, 2 * DM, d * DM, DI);
    }

    gemm_kernel<2><<<dim3(MB, DM / 64), 256>>>(cat, 2 * DM, merge_W, merge_b, x,
                                               x1, DM, 0, 2 * DM);
    ln_kernel<<<MT, 256>>>(x1, g2, b2, xn2);
    gemm_kernel<3><<<dim3(MB, 4 * DM / 64), 256>>>(xn2, DM, ffn_W1, ffn_b1, nullptr,
                                                   hff, 4 * DM, 0, DM);
    gemm_kernel<2><<<dim3(MB, DM / 64), 256>>>(hff, 4 * DM, ffn_W2, ffn_b2, x1,
                                               (float*)d_out, DM, 0, 4 * DM);
}

// round 2
// speedup vs baseline: 1.9289x; 1.9289x over previous
#include <cuda_runtime.h>
#include <cstdint>

#define BB 4
#define NN 576
#define DM 512
#define DI 1024
#define DS 16
#define DTR 32
#define MT (BB*NN)   // 2304 tokens

// ---------------- workspace ----------------
#define SZ_XN   (MT*DM)
#define SZ_XZ   (MT*2*DI)
#define SZ_U    (MT*DI)
#define SZ_XD   (MT*64)
#define SZ_DT   (MT*DI)
#define SZ_Y    (MT*DI)
#define SZ_CAT  (MT*2*DM)
#define SZ_X1   (MT*DM)
#define SZ_XN2  (MT*DM)
#define SZ_HFF  (MT*4*DM)

#define OFF_XN   0
#define OFF_XZ0  (OFF_XN + SZ_XN)
#define OFF_XZ1  (OFF_XZ0 + SZ_XZ)
#define OFF_U0   (OFF_XZ1 + SZ_XZ)
#define OFF_U1   (OFF_U0 + SZ_U)
#define OFF_XD0  (OFF_U1 + SZ_U)
#define OFF_XD1  (OFF_XD0 + SZ_XD)
#define OFF_DT0  (OFF_XD1 + SZ_XD)
#define OFF_DT1  (OFF_DT0 + SZ_DT)
#define OFF_Y0   (OFF_DT1 + SZ_DT)
#define OFF_Y1   (OFF_Y0 + SZ_Y)
#define OFF_CAT  (OFF_Y1 + SZ_Y)
#define OFF_X1   (OFF_CAT + SZ_CAT)
#define OFF_XN2  (OFF_X1 + SZ_X1)
#define OFF_HFF  (OFF_XN2 + SZ_XN2)
#define WS_TOTAL (OFF_HFF + SZ_HFF)

__device__ float g_ws[WS_TOTAL];

// ---------------- helpers ----------------
__device__ __forceinline__ float sigmoidf_(float x) { return 1.f / (1.f + __expf(-x)); }
__device__ __forceinline__ float softplusf_(float x) {
    return fmaxf(x, 0.f) + log1pf(__expf(-fabsf(x)));
}
__device__ __forceinline__ float gelu_tanh(float x) {
    float x3 = x * x * x;
    return 0.5f * x * (1.f + tanhf(0.7978845608028654f * (x + 0.044715f * x3)));
}

// ---------------- LayerNorm ----------------
__global__ void ln_kernel(const float* __restrict__ x, const float* __restrict__ g,
                          const float* __restrict__ b, float* __restrict__ out) {
    int row = blockIdx.x;
    int t = threadIdx.x;              // 256 threads
    const float* xr = x + row * DM;
    float v0 = xr[t], v1 = xr[t + 256];
    float s = v0 + v1, q = v0 * v0 + v1 * v1;
    #pragma unroll
    for (int o = 16; o; o >>= 1) {
        s += __shfl_xor_sync(0xffffffffu, s, o);
        q += __shfl_xor_sync(0xffffffffu, q, o);
    }
    __shared__ float ss[8], qq[8];
    int w = t >> 5;
    if ((t & 31) == 0) { ss[w] = s; qq[w] = q; }
    __syncthreads();
    s = 0.f; q = 0.f;
    #pragma unroll
    for (int i = 0; i < 8; i++) { s += ss[i]; q += qq[i]; }
    float mean = s * (1.f / DM);
    float var = q * (1.f / DM) - mean * mean;
    float inv = rsqrtf(var + 1e-5f);
    out[row * DM + t]       = (v0 - mean) * inv * g[t] + b[t];
    out[row * DM + t + 256] = (v1 - mean) * inv * g[t + 256] + b[t + 256];
}

// ---------------- tf32 tensor-core GEMM ----------------
// C[m, coff+n] = A(MxK, lda) @ W(NxK)^T  (+epilogue)
// EPI: 0 none, 1 bias+softplus, 2 bias+residual, 3 bias+gelu
struct PtrSet {
    const float* A;
    const float* W;
    const float* bias;
    const float* resid;
    float* C;
};

__device__ __forceinline__ void mma8(float (&d)[4], const float (&a)[4], const float (&b)[2]) {
    asm volatile(
        "mma.sync.aligned.m16n8k8.row.col.f32.tf32.tf32.f32 "
        "{%0,%1,%2,%3}, {%4,%5,%6,%7}, {%8,%9}, {%0,%1,%2,%3};\n"
        : "+f"(d[0]), "+f"(d[1]), "+f"(d[2]), "+f"(d[3])
        : "r"(__float_as_uint(a[0])), "r"(__float_as_uint(a[1])),
          "r"(__float_as_uint(a[2])), "r"(__float_as_uint(a[3])),
          "r"(__float_as_uint(b[0])), "r"(__float_as_uint(b[1])));
}

#define CP16(dst, src) \
    asm volatile("cp.async.ca.shared.global [%0], [%1], 16;\n" :: "r"(dst), "l"(src))
#define CP16Z(dst, src, sz) \
    asm volatile("cp.async.ca.shared.global [%0], [%1], 16, %2;\n" :: "r"(dst), "l"(src), "r"(sz))
#define CPCOMMIT() asm volatile("cp.async.commit_group;\n")
#define CPWAIT1()  asm volatile("cp.async.wait_group 1;\n")

#define SROW 20   // padded k-stride (floats): banks 4g+t conflict-free, 16B aligned

template <int EPI>
__global__ void __launch_bounds__(256, 2) mm_tf32(
    PtrSet p0, PtrSet p1, int lda, int ldc, int coffStep, int N, int K)
{
    __shared__ float As[2][128 * SROW];
    __shared__ float Bs[2][128 * SROW];

    const PtrSet p = blockIdx.z ? p1 : p0;
    const int coff = blockIdx.z * coffStep;

    const int tid = threadIdx.x;
    const int lane = tid & 31;
    const int wid = tid >> 5;
    const int wr = wid >> 2;       // 0..1  (M)
    const int wc = wid & 3;        // 0..3  (N)
    const int g = lane >> 2;       // 0..7
    const int t = lane & 3;        // 0..3

    const int m0 = blockIdx.x * 128;
    const int n0 = blockIdx.y * 128;

    const int lrow = tid >> 2;             // 0..63
    const int kq = (tid & 3) * 4;          // 0,4,8,12

    const uint32_t asb = (uint32_t)__cvta_generic_to_shared(&As[0][0]);
    const uint32_t bsb = (uint32_t)__cvta_generic_to_shared(&Bs[0][0]);

    float d[4][4][4];
    #pragma unroll
    for (int i = 0; i < 4; i++)
        #pragma unroll
        for (int j = 0; j < 4; j++)
            #pragma unroll
            for (int r = 0; r < 4; r++) d[i][j][r] = 0.f;

    const int nc = K >> 4;   // K/16 chunks

    // ---- loader ----
    #define LOAD_STAGE(s, k0) do {                                               \
        const float* asrc = p.A + (size_t)(m0 + lrow) * lda + (k0) + kq;         \
        uint32_t adst = asb + (uint32_t)(((s) * 128 * SROW + lrow * SROW + kq) * 4); \
        CP16(adst, asrc);                                                         \
        CP16(adst + 64 * SROW * 4, asrc + (size_t)64 * lda);                      \
        int nr0 = n0 + lrow;                                                      \
        const float* bsrc = p.W + (size_t)nr0 * K + (k0) + kq;                    \
        uint32_t bdst = bsb + (uint32_t)(((s) * 128 * SROW + lrow * SROW + kq) * 4); \
        CP16Z(bdst, bsrc, nr0 < N ? 16 : 0);                                      \
        CP16Z(bdst + 64 * SROW * 4, bsrc + (size_t)64 * K, (nr0 + 64) < N ? 16 : 0); \
    } while (0)

    LOAD_STAGE(0, 0);
    CPCOMMIT();

    for (int c = 0; c < nc; c++) {
        if (c + 1 < nc) LOAD_STAGE((c + 1) & 1, (c + 1) * 16);
        CPCOMMIT();
        CPWAIT1();
        __syncthreads();

        const int s = c & 1;
        #pragma unroll
        for (int kk = 0; kk < 2; kk++) {
            float a[4][4];
            float b[4][2];
            const float* Ab = &As[s][(wr * 64) * SROW + kk * 8];
            #pragma unroll
            for (int mt = 0; mt < 4; mt++) {
                const float* q = Ab + mt * 16 * SROW;
                a[mt][0] = q[g * SROW + t];
                a[mt][1] = q[(g + 8) * SROW + t];
                a[mt][2] = q[g * SROW + t + 4];
                a[mt][3] = q[(g + 8) * SROW + t + 4];
            }
            const float* Bb = &Bs[s][(wc * 32) * SROW + kk * 8];
            #pragma unroll
            for (int nt = 0; nt < 4; nt++) {
                const float* q = Bb + nt * 8 * SROW;
                b[nt][0] = q[g * SROW + t];
                b[nt][1] = q[g * SROW + t + 4];
            }
            #pragma unroll
            for (int mt = 0; mt < 4; mt++)
                #pragma unroll
                for (int nt = 0; nt < 4; nt++)
                    mma8(d[mt][nt], a[mt], b[nt]);
        }
        __syncthreads();
    }
    #undef LOAD_STAGE

    // ---- epilogue ----
    #pragma unroll
    for (int mt = 0; mt < 4; mt++) {
        const int row = m0 + wr * 64 + mt * 16 + g;
        #pragma unroll
        for (int nt = 0; nt < 4; nt++) {
            const int col = n0 + wc * 32 + nt * 8 + 2 * t;
            if (col < N) {
                float v00 = d[mt][nt][0], v01 = d[mt][nt][1];
                float v10 = d[mt][nt][2], v11 = d[mt][nt][3];
                if (EPI != 0) {
                    float bz0 = p.bias[col], bz1 = p.bias[col + 1];
                    v00 += bz0; v01 += bz1; v10 += bz0; v11 += bz1;
                }
                if (EPI == 1) {
                    v00 = softplusf_(v00); v01 = softplusf_(v01);
                    v10 = softplusf_(v10); v11 = softplusf_(v11);
                } else if (EPI == 2) {
                    const float* r0 = p.resid + (size_t)row * ldc + coff + col;
                    const float* r1 = p.resid + (size_t)(row + 8) * ldc + coff + col;
                    v00 += r0[0]; v01 += r0[1]; v10 += r1[0]; v11 += r1[1];
                } else if (EPI == 3) {
                    v00 = gelu_tanh(v00); v01 = gelu_tanh(v01);
                    v10 = gelu_tanh(v10); v11 = gelu_tanh(v11);
                }
                *(float2*)&p.C[(size_t)row * ldc + coff + col]       = make_float2(v00, v01);
                *(float2*)&p.C[(size_t)(row + 8) * ldc + coff + col] = make_float2(v10, v11);
            }
        }
    }
}

// ---------------- depthwise causal conv + SiLU ----------------
__global__ void conv_kernel(const float* __restrict__ xz0, const float* __restrict__ xz1,
                            const float* __restrict__ w0, const float* __restrict__ w1,
                            const float* __restrict__ cb0, const float* __restrict__ cb1,
                            float* __restrict__ u0, float* __restrict__ u1)
{
    int dir = blockIdx.y;
    const float* xz = dir ? xz1 : xz0;
    const float* w  = dir ? w1  : w0;
    const float* cb = dir ? cb1 : cb0;
    float* u        = dir ? u1  : u0;

    int i = blockIdx.x * 256 + threadIdx.x;
    if (i >= MT * DI) return;
    int c = i % DI;
    int row = i / DI;
    int n = row % NN, b = row / NN;
    float acc = cb[c];
    #pragma unroll
    for (int k = 0; k < 4; k++) {
        int nn = dir ? (n + 3 - k) : (n - 3 + k);
        if (nn >= 0 && nn < NN)
            acc += xz[(size_t)(b * NN + nn) * 2 * DI + c] * w[c * 4 + k];
    }
    u[i] = acc * sigmoidf_(acc);
}

// ---------------- selective scan ----------------
#define PF 6
__global__ void __launch_bounds__(512, 1) scan_kernel(
    const float* __restrict__ u0p, const float* __restrict__ u1p,
    const float* __restrict__ dt0p, const float* __restrict__ dt1p,
    const float* __restrict__ xd0p, const float* __restrict__ xd1p,
    const float* __restrict__ xz0p, const float* __restrict__ xz1p,
    const float* __restrict__ Al0, const float* __restrict__ Al1,
    const float* __restrict__ D0p, const float* __restrict__ D1p,
    float* __restrict__ y0p, float* __restrict__ y1p)
{
    const int dir = blockIdx.y;
    const float* up   = dir ? u1p  : u0p;
    const float* dtp  = dir ? dt1p : dt0p;
    const float* xdp  = dir ? xd1p : xd0p;
    const float* xzp  = dir ? xz1p : xz0p;
    const float* Alog = dir ? Al1  : Al0;
    const float* Dp   = dir ? D1p  : D0p;
    float* yp         = dir ? y1p  : y0p;

    __shared__ __align__(16) float sm[PF][224];
    const int bi = blockIdx.x >> 4;
    const int cb = (blockIdx.x & 15) << 6;
    const int tid = threadIdx.x;
    const int s = tid & 15;
    const int cl0 = tid >> 4;
    const int c0 = cb + cl0, c1 = c0 + 32;

    const float A0 = -__expf(Alog[c0 * DS + s]);
    const float A1 = -__expf(Alog[c1 * DS + s]);
    const float Dc0 = Dp[c0], Dc1 = Dp[c1];
    float h0 = 0.f, h1 = 0.f;

    auto issue = [&](int stage, int n) {
        if (tid < 56) {
            int row = bi * NN + n;
            const float* src;
            int off;
            if (tid < 16)      { src = dtp + (size_t)row * DI + cb + tid * 4;               off = tid * 4; }
            else if (tid < 32) { src = up  + (size_t)row * DI + cb + (tid - 16) * 4;        off = 64 + (tid - 16) * 4; }
            else if (tid < 48) { src = xzp + (size_t)row * 2 * DI + DI + cb + (tid - 32) * 4; off = 128 + (tid - 32) * 4; }
            else if (tid < 52) { src = xdp + (size_t)row * 64 + 32 + (tid - 48) * 4;        off = 192 + (tid - 48) * 4; }
            else               { src = xdp + (size_t)row * 64 + 48 + (tid - 52) * 4;        off = 208 + (tid - 52) * 4; }
            uint32_t d = (uint32_t)__cvta_generic_to_shared(&sm[stage][off]);
            asm volatile("cp.async.ca.shared.global [%0], [%1], 16;\n" :: "r"(d), "l"(src));
        }
    };
    #define NIDX(st) (dir ? (NN - 1 - (st)) : (st))

    issue(0, NIDX(0)); asm volatile("cp.async.commit_group;");
    issue(1, NIDX(1)); asm volatile("cp.async.commit_group;");
    issue(2, NIDX(2)); asm volatile("cp.async.commit_group;");

    for (int step = 0; step < NN; step++) {
        if (step + 3 < NN) issue((step + 3) % PF, NIDX(step + 3));
        asm volatile("cp.async.commit_group;");
        asm volatile("cp.async.wait_group 3;");
        __syncthreads();
        const float* S = sm[step % PF];
        float dt0 = S[cl0],      dt1 = S[32 + cl0];
        float u0v = S[64 + cl0], u1v = S[96 + cl0];
        float Bv = S[192 + s],   Cv = S[208 + s];
        h0 = __expf(dt0 * A0) * h0 + dt0 * Bv * u0v;
        h1 = __expf(dt1 * A1) * h1 + dt1 * Bv * u1v;
        float y0 = h0 * Cv, y1 = h1 * Cv;
        #pragma unroll
        for (int o = 8; o; o >>= 1) {
            y0 += __shfl_xor_sync(0xffffffffu, y0, o);
            y1 += __shfl_xor_sync(0xffffffffu, y1, o);
        }
        if (s == 0) {
            int row = bi * NN + NIDX(step);
            float z0 = S[128 + cl0], z1 = S[160 + cl0];
            yp[(size_t)row * DI + c0] = (y0 + u0v * Dc0) * (z0 * sigmoidf_(z0));
            yp[(size_t)row * DI + c1] = (y1 + u1v * Dc1) * (z1 * sigmoidf_(z1));
        }
    }
    #undef NIDX
}

// ---------------- launch ----------------
extern "C" void kernel_launch(void* const* d_in, const int* in_sizes, int n_in,
                              void* d_out, int out_size) {
    const float* x  = (const float*)d_in[0];
    const float* g1 = (const float*)d_in[1];
    const float* b1 = (const float*)d_in[2];
    const float* g2 = (const float*)d_in[3];
    const float* b2 = (const float*)d_in[4];

    int base_f, base_r, base_m;
    if (in_sizes[5] == DM * 2 * DM) {        // merge_W first => dict order
        base_m = 5; base_f = 11; base_r = 20;
    } else {                                  // f_Win first => signature order
        base_f = 5; base_r = 14; base_m = 23;
    }
    const float *Win[2], *convw[2], *convb[2], *Wx[2], *Wdt[2], *bdt[2], *Alog[2], *Dp[2], *Wout[2];
    int bases[2] = {base_f, base_r};
    for (int d = 0; d < 2; d++) {
        int bs = bases[d];
        Win[d]   = (const float*)d_in[bs + 0];
        convw[d] = (const float*)d_in[bs + 1];
        convb[d] = (const float*)d_in[bs + 2];
        Wx[d]    = (const float*)d_in[bs + 3];
        Wdt[d]   = (const float*)d_in[bs + 4];
        bdt[d]   = (const float*)d_in[bs + 5];
        Alog[d]  = (const float*)d_in[bs + 6];
        Dp[d]    = (const float*)d_in[bs + 7];
        Wout[d]  = (const float*)d_in[bs + 8];
    }
    const float* merge_W = (const float*)d_in[base_m + 0];
    const float* merge_b = (const float*)d_in[base_m + 1];
    const float* ffn_W1  = (const float*)d_in[base_m + 2];
    const float* ffn_b1  = (const float*)d_in[base_m + 3];
    const float* ffn_W2  = (const float*)d_in[base_m + 4];
    const float* ffn_b2  = (const float*)d_in[base_m + 5];

    float* ws = nullptr;
    cudaGetSymbolAddress((void**)&ws, g_ws);
    float* xn  = ws + OFF_XN;
    float* xz[2]  = {ws + OFF_XZ0, ws + OFF_XZ1};
    float* u[2]   = {ws + OFF_U0,  ws + OFF_U1};
    float* xd[2]  = {ws + OFF_XD0, ws + OFF_XD1};
    float* dt[2]  = {ws + OFF_DT0, ws + OFF_DT1};
    float* y[2]   = {ws + OFF_Y0,  ws + OFF_Y1};
    float* cat = ws + OFF_CAT;
    float* x1  = ws + OFF_X1;
    float* xn2 = ws + OFF_XN2;
    float* hff = ws + OFF_HFF;

    const int MTB = MT / 128;  // 18

    ln_kernel<<<MT, 256>>>(x, g1, b1, xn);

    // in-proj for both directions
    {
        PtrSet a{xn, Win[0], nullptr, nullptr, xz[0]};
        PtrSet b{xn, Win[1], nullptr, nullptr, xz[1]};
        mm_tf32<0><<<dim3(MTB, 16, 2), 256>>>(a, b, DM, 2 * DI, 0, 2 * DI, DM);
    }

    conv_kernel<<<dim3((MT * DI + 255) / 256, 2), 256>>>(
        xz[0], xz[1], convw[0], convw[1], convb[0], convb[1], u[0], u[1]);

    // x-proj (N=64) both dirs
    {
        PtrSet a{u[0], Wx[0], nullptr, nullptr, xd[0]};
        PtrSet b{u[1], Wx[1], nullptr, nullptr, xd[1]};
        mm_tf32<0><<<dim3(MTB, 1, 2), 256>>>(a, b, DI, 64, 0, 64, DI);
    }

    // dt-proj + softplus, both dirs
    {
        PtrSet a{xd[0], Wdt[0], bdt[0], nullptr, dt[0]};
        PtrSet b{xd[1], Wdt[1], bdt[1], nullptr, dt[1]};
        mm_tf32<1><<<dim3(MTB, 8, 2), 256>>>(a, b, 64, DI, 0, DI, DTR);
    }

    scan_kernel<<<dim3(BB * (DI / 64), 2), 512>>>(
        u[0], u[1], dt[0], dt[1], xd[0], xd[1], xz[0], xz[1],
        Alog[0], Alog[1], Dp[0], Dp[1], y[0], y[1]);

    // out-proj both dirs -> cat
    {
        PtrSet a{y[0], Wout[0], nullptr, nullptr, cat};
        PtrSet b{y[1], Wout[1], nullptr, nullptr, cat};
        mm_tf32<0><<<dim3(MTB, 4, 2), 256>>>(a, b, DI, 2 * DM, DM, DM, DI);
    }

    // merge + residual
    {
        PtrSet a{cat, merge_W, merge_b, x, x1};
        mm_tf32<2><<<dim3(MTB, 4, 1), 256>>>(a, a, 2 * DM, DM, 0, DM, 2 * DM);
    }

    ln_kernel<<<MT, 256>>>(x1, g2, b2, xn2);

    // ffn1 + gelu
    {
        PtrSet a{xn2, ffn_W1, ffn_b1, nullptr, hff};
        mm_tf32<3><<<dim3(MTB, 16, 1), 256>>>(a, a, DM, 4 * DM, 0, 4 * DM, DM);
    }
    // ffn2 + residual -> out
    {
        PtrSet a{hff, ffn_W2, ffn_b2, x1, (float*)d_out};
        mm_tf32<2><<<dim3(MTB, 4, 1), 256>>>(a, a, 4 * DM, DM, 0, DM, 4 * DM);
    }
}

// round 3
// speedup vs baseline: 2.1841x; 1.1323x over previous
#include <cuda_runtime.h>
#include <cstdint>

#define BB 4
#define NN 576
#define DM 512
#define DI 1024
#define DS 16
#define DTR 32
#define MT (BB*NN)   // 2304 tokens

// ---------------- workspace ----------------
#define SZ_XN   (MT*DM)
#define SZ_XZ   (MT*2*DI)
#define SZ_U    (MT*DI)
#define SZ_XD   (MT*64)
#define SZ_DT   (MT*DI)
#define SZ_Y    (MT*DI)
#define SZ_CAT  (MT*2*DM)
#define SZ_X1   (MT*DM)
#define SZ_XN2  (MT*DM)
#define SZ_HFF  (MT*4*DM)

#define OFF_XN   0
#define OFF_XZ0  (OFF_XN + SZ_XN)
#define OFF_XZ1  (OFF_XZ0 + SZ_XZ)
#define OFF_U0   (OFF_XZ1 + SZ_XZ)
#define OFF_U1   (OFF_U0 + SZ_U)
#define OFF_XD0  (OFF_U1 + SZ_U)
#define OFF_XD1  (OFF_XD0 + SZ_XD)
#define OFF_DT0  (OFF_XD1 + SZ_XD)
#define OFF_DT1  (OFF_DT0 + SZ_DT)
#define OFF_Y0   (OFF_DT1 + SZ_DT)
#define OFF_Y1   (OFF_Y0 + SZ_Y)
#define OFF_CAT  (OFF_Y1 + SZ_Y)
#define OFF_X1   (OFF_CAT + SZ_CAT)
#define OFF_XN2  (OFF_X1 + SZ_X1)
#define OFF_HFF  (OFF_XN2 + SZ_XN2)
#define WS_TOTAL (OFF_HFF + SZ_HFF)

__device__ float g_ws[WS_TOTAL];

// ---------------- helpers ----------------
__device__ __forceinline__ float sigmoidf_(float x) { return 1.f / (1.f + __expf(-x)); }
__device__ __forceinline__ float softplusf_(float x) {
    return fmaxf(x, 0.f) + log1pf(__expf(-fabsf(x)));
}
__device__ __forceinline__ float gelu_tanh(float x) {
    float x3 = x * x * x;
    return 0.5f * x * (1.f + tanhf(0.7978845608028654f * (x + 0.044715f * x3)));
}

// ---------------- LayerNorm ----------------
__global__ void ln_kernel(const float* __restrict__ x, const float* __restrict__ g,
                          const float* __restrict__ b, float* __restrict__ out) {
    int row = blockIdx.x;
    int t = threadIdx.x;              // 256 threads
    const float* xr = x + row * DM;
    float v0 = xr[t], v1 = xr[t + 256];
    float s = v0 + v1, q = v0 * v0 + v1 * v1;
    #pragma unroll
    for (int o = 16; o; o >>= 1) {
        s += __shfl_xor_sync(0xffffffffu, s, o);
        q += __shfl_xor_sync(0xffffffffu, q, o);
    }
    __shared__ float ss[8], qq[8];
    int w = t >> 5;
    if ((t & 31) == 0) { ss[w] = s; qq[w] = q; }
    __syncthreads();
    s = 0.f; q = 0.f;
    #pragma unroll
    for (int i = 0; i < 8; i++) { s += ss[i]; q += qq[i]; }
    float mean = s * (1.f / DM);
    float var = q * (1.f / DM) - mean * mean;
    float inv = rsqrtf(var + 1e-5f);
    out[row * DM + t]       = (v0 - mean) * inv * g[t] + b[t];
    out[row * DM + t + 256] = (v1 - mean) * inv * g[t + 256] + b[t + 256];
}

// ---------------- tf32 tensor-core GEMM (ldmatrix fragments, 3-stage pipeline) ----------------
// C[m, coff+n] = A(MxK, lda) @ W(NxK)^T  (+epilogue)
// EPI: 0 none, 1 bias+softplus, 2 bias+residual, 3 bias+gelu
struct PtrSet {
    const float* A;
    const float* W;
    const float* bias;
    const float* resid;
    float* C;
};

__device__ __forceinline__ void mma8(float (&d)[4], const uint32_t (&a)[4], const uint32_t (&b)[2]) {
    asm volatile(
        "mma.sync.aligned.m16n8k8.row.col.f32.tf32.tf32.f32 "
        "{%0,%1,%2,%3}, {%4,%5,%6,%7}, {%8,%9}, {%0,%1,%2,%3};\n"
        : "+f"(d[0]), "+f"(d[1]), "+f"(d[2]), "+f"(d[3])
        : "r"(a[0]), "r"(a[1]), "r"(a[2]), "r"(a[3]),
          "r"(b[0]), "r"(b[1]));
}

__device__ __forceinline__ void ldsm4(uint32_t (&r)[4], uint32_t addr) {
    asm volatile("ldmatrix.sync.aligned.m8n8.x4.shared.b16 {%0,%1,%2,%3}, [%4];\n"
                 : "=r"(r[0]), "=r"(r[1]), "=r"(r[2]), "=r"(r[3]) : "r"(addr));
}

#define CP16(dst, src) \
    asm volatile("cp.async.ca.shared.global [%0], [%1], 16;\n" :: "r"(dst), "l"(src))
#define CP16Z(dst, src, sz) \
    asm volatile("cp.async.ca.shared.global [%0], [%1], 16, %2;\n" :: "r"(dst), "l"(src), "r"(sz))
#define CPCOMMIT() asm volatile("cp.async.commit_group;\n")
#define CPWAIT1()  asm volatile("cp.async.wait_group 1;\n")

#define SROW 20              // padded k-stride (floats)
#define STG  3               // pipeline stages
#define STAGE_F (128 * SROW) // floats per stage per operand
#define SMEM_BYTES (STG * STAGE_F * 2 * 4)

template <int EPI>
__global__ void __launch_bounds__(256, 2) mm_tf32(
    PtrSet p0, PtrSet p1, int lda, int ldc, int coffStep, int N, int K)
{
    extern __shared__ float dynsm[];
    float* Asm = dynsm;
    float* Bsm = dynsm + STG * STAGE_F;

    const PtrSet p = blockIdx.z ? p1 : p0;
    const int coff = blockIdx.z * coffStep;

    const int tid = threadIdx.x;
    const int lane = tid & 31;
    const int wid = tid >> 5;
    const int wr = wid >> 2;       // 0..1  (M)
    const int wc = wid & 3;        // 0..3  (N)
    const int g = lane >> 2;       // 0..7
    const int t = lane & 3;        // 0..3

    const int m0 = blockIdx.x * 128;
    const int n0 = blockIdx.y * 128;

    const int lrow = tid >> 2;             // 0..63
    const int kq = (tid & 3) * 4;          // 0,4,8,12

    const uint32_t asb = (uint32_t)__cvta_generic_to_shared(Asm);
    const uint32_t bsb = (uint32_t)__cvta_generic_to_shared(Bsm);

    // ldmatrix per-lane address components
    // A: matrices (rows 0-7 k0-3 | rows 8-15 k0-3 | rows 0-7 k4-7 | rows 8-15 k4-7)
    const uint32_t a_off = (uint32_t)(((wr * 64 + (lane & 15)) * SROW + (lane >> 4) * 4) * 4);
    // B: pair of n-tiles; matrices (nt rows k0-3 | nt rows k4-7 | nt+1 rows k0-3 | nt+1 rows k4-7)
    const uint32_t b_off = (uint32_t)(((wc * 32 + (lane & 7) + ((lane >> 4) << 3)) * SROW
                                       + ((lane >> 3) & 1) * 4) * 4);

    float d[4][4][4];
    #pragma unroll
    for (int i = 0; i < 4; i++)
        #pragma unroll
        for (int j = 0; j < 4; j++)
            #pragma unroll
            for (int r = 0; r < 4; r++) d[i][j][r] = 0.f;

    const int nc = K >> 4;   // K/16 chunks

    #define LOAD_STAGE(s, k0) do {                                               \
        const float* asrc = p.A + (size_t)(m0 + lrow) * lda + (k0) + kq;         \
        uint32_t adst = asb + (uint32_t)(((s) * STAGE_F + lrow * SROW + kq) * 4); \
        CP16(adst, asrc);                                                         \
        CP16(adst + 64 * SROW * 4, asrc + (size_t)64 * lda);                      \
        int nr0 = n0 + lrow;                                                      \
        const float* bsrc = p.W + (size_t)nr0 * K + (k0) + kq;                    \
        uint32_t bdst = bsb + (uint32_t)(((s) * STAGE_F + lrow * SROW + kq) * 4); \
        CP16Z(bdst, bsrc, nr0 < N ? 16 : 0);                                      \
        CP16Z(bdst + 64 * SROW * 4, bsrc + (size_t)64 * K, (nr0 + 64) < N ? 16 : 0); \
    } while (0)

    LOAD_STAGE(0, 0);
    CPCOMMIT();
    if (nc > 1) LOAD_STAGE(1, 16);
    CPCOMMIT();

    for (int c = 0; c < nc; c++) {
        CPWAIT1();
        __syncthreads();
        if (c + 2 < nc) LOAD_STAGE((c + 2) % STG, (c + 2) * 16);
        CPCOMMIT();

        const uint32_t sa = asb + (uint32_t)((c % STG) * STAGE_F * 4);
        const uint32_t sb = bsb + (uint32_t)((c % STG) * STAGE_F * 4);
        #pragma unroll
        for (int kk = 0; kk < 2; kk++) {
            uint32_t a[4][4];
            uint32_t b[4][2];
            #pragma unroll
            for (int mt = 0; mt < 4; mt++)
                ldsm4(a[mt], sa + a_off + (uint32_t)((mt * 16 * SROW + kk * 8) * 4));
            #pragma unroll
            for (int np = 0; np < 2; np++) {
                uint32_t r[4];
                ldsm4(r, sb + b_off + (uint32_t)((np * 16 * SROW + kk * 8) * 4));
                b[2 * np][0] = r[0]; b[2 * np][1] = r[1];
                b[2 * np + 1][0] = r[2]; b[2 * np + 1][1] = r[3];
            }
            #pragma unroll
            for (int mt = 0; mt < 4; mt++)
                #pragma unroll
                for (int nt = 0; nt < 4; nt++)
                    mma8(d[mt][nt], a[mt], b[nt]);
        }
    }
    #undef LOAD_STAGE

    // ---- epilogue ----
    #pragma unroll
    for (int mt = 0; mt < 4; mt++) {
        const int row = m0 + wr * 64 + mt * 16 + g;
        #pragma unroll
        for (int nt = 0; nt < 4; nt++) {
            const int col = n0 + wc * 32 + nt * 8 + 2 * t;
            if (col < N) {
                float v00 = d[mt][nt][0], v01 = d[mt][nt][1];
                float v10 = d[mt][nt][2], v11 = d[mt][nt][3];
                if (EPI != 0) {
                    float bz0 = p.bias[col], bz1 = p.bias[col + 1];
                    v00 += bz0; v01 += bz1; v10 += bz0; v11 += bz1;
                }
                if (EPI == 1) {
                    v00 = softplusf_(v00); v01 = softplusf_(v01);
                    v10 = softplusf_(v10); v11 = softplusf_(v11);
                } else if (EPI == 2) {
                    const float* r0 = p.resid + (size_t)row * ldc + coff + col;
                    const float* r1 = p.resid + (size_t)(row + 8) * ldc + coff + col;
                    v00 += r0[0]; v01 += r0[1]; v10 += r1[0]; v11 += r1[1];
                } else if (EPI == 3) {
                    v00 = gelu_tanh(v00); v01 = gelu_tanh(v01);
                    v10 = gelu_tanh(v10); v11 = gelu_tanh(v11);
                }
                *(float2*)&p.C[(size_t)row * ldc + coff + col]       = make_float2(v00, v01);
                *(float2*)&p.C[(size_t)(row + 8) * ldc + coff + col] = make_float2(v10, v11);
            }
        }
    }
}

// ---------------- depthwise causal conv + SiLU ----------------
__global__ void conv_kernel(const float* __restrict__ xz0, const float* __restrict__ xz1,
                            const float* __restrict__ w0, const float* __restrict__ w1,
                            const float* __restrict__ cb0, const float* __restrict__ cb1,
                            float* __restrict__ u0, float* __restrict__ u1)
{
    int dir = blockIdx.y;
    const float* xz = dir ? xz1 : xz0;
    const float* w  = dir ? w1  : w0;
    const float* cb = dir ? cb1 : cb0;
    float* u        = dir ? u1  : u0;

    int i = blockIdx.x * 256 + threadIdx.x;
    if (i >= MT * DI) return;
    int c = i % DI;
    int row = i / DI;
    int n = row % NN, b = row / NN;
    float acc = cb[c];
    #pragma unroll
    for (int k = 0; k < 4; k++) {
        int nn = dir ? (n + 3 - k) : (n - 3 + k);
        if (nn >= 0 && nn < NN)
            acc += xz[(size_t)(b * NN + nn) * 2 * DI + c] * w[c * 4 + k];
    }
    u[i] = acc * sigmoidf_(acc);
}

// ---------------- selective scan ----------------
#define PF 6
__global__ void __launch_bounds__(512, 1) scan_kernel(
    const float* __restrict__ u0p, const float* __restrict__ u1p,
    const float* __restrict__ dt0p, const float* __restrict__ dt1p,
    const float* __restrict__ xd0p, const float* __restrict__ xd1p,
    const float* __restrict__ xz0p, const float* __restrict__ xz1p,
    const float* __restrict__ Al0, const float* __restrict__ Al1,
    const float* __restrict__ D0p, const float* __restrict__ D1p,
    float* __restrict__ y0p, float* __restrict__ y1p)
{
    const int dir = blockIdx.y;
    const float* up   = dir ? u1p  : u0p;
    const float* dtp  = dir ? dt1p : dt0p;
    const float* xdp  = dir ? xd1p : xd0p;
    const float* xzp  = dir ? xz1p : xz0p;
    const float* Alog = dir ? Al1  : Al0;
    const float* Dp   = dir ? D1p  : D0p;
    float* yp         = dir ? y1p  : y0p;

    __shared__ __align__(16) float sm[PF][224];
    const int bi = blockIdx.x >> 4;
    const int cb = (blockIdx.x & 15) << 6;
    const int tid = threadIdx.x;
    const int s = tid & 15;
    const int cl0 = tid >> 4;
    const int c0 = cb + cl0, c1 = c0 + 32;

    const float A0 = -__expf(Alog[c0 * DS + s]);
    const float A1 = -__expf(Alog[c1 * DS + s]);
    const float Dc0 = Dp[c0], Dc1 = Dp[c1];
    float h0 = 0.f, h1 = 0.f;

    auto issue = [&](int stage, int n) {
        if (tid < 56) {
            int row = bi * NN + n;
            const float* src;
            int off;
            if (tid < 16)      { src = dtp + (size_t)row * DI + cb + tid * 4;               off = tid * 4; }
            else if (tid < 32) { src = up  + (size_t)row * DI + cb + (tid - 16) * 4;        off = 64 + (tid - 16) * 4; }
            else if (tid < 48) { src = xzp + (size_t)row * 2 * DI + DI + cb + (tid - 32) * 4; off = 128 + (tid - 32) * 4; }
            else if (tid < 52) { src = xdp + (size_t)row * 64 + 32 + (tid - 48) * 4;        off = 192 + (tid - 48) * 4; }
            else               { src = xdp + (size_t)row * 64 + 48 + (tid - 52) * 4;        off = 208 + (tid - 52) * 4; }
            uint32_t d = (uint32_t)__cvta_generic_to_shared(&sm[stage][off]);
            asm volatile("cp.async.ca.shared.global [%0], [%1], 16;\n" :: "r"(d), "l"(src));
        }
    };
    #define NIDX(st) (dir ? (NN - 1 - (st)) : (st))

    issue(0, NIDX(0)); asm volatile("cp.async.commit_group;");
    issue(1, NIDX(1)); asm volatile("cp.async.commit_group;");
    issue(2, NIDX(2)); asm volatile("cp.async.commit_group;");

    for (int step = 0; step < NN; step++) {
        if (step + 3 < NN) issue((step + 3) % PF, NIDX(step + 3));
        asm volatile("cp.async.commit_group;");
        asm volatile("cp.async.wait_group 3;");
        __syncthreads();
        const float* S = sm[step % PF];
        float dt0 = S[cl0],      dt1 = S[32 + cl0];
        float u0v = S[64 + cl0], u1v = S[96 + cl0];
        float Bv = S[192 + s],   Cv = S[208 + s];
        h0 = __expf(dt0 * A0) * h0 + dt0 * Bv * u0v;
        h1 = __expf(dt1 * A1) * h1 + dt1 * Bv * u1v;
        float y0 = h0 * Cv, y1 = h1 * Cv;
        #pragma unroll
        for (int o = 8; o; o >>= 1) {
            y0 += __shfl_xor_sync(0xffffffffu, y0, o);
            y1 += __shfl_xor_sync(0xffffffffu, y1, o);
        }
        if (s == 0) {
            int row = bi * NN + NIDX(step);
            float z0 = S[128 + cl0], z1 = S[160 + cl0];
            yp[(size_t)row * DI + c0] = (y0 + u0v * Dc0) * (z0 * sigmoidf_(z0));
            yp[(size_t)row * DI + c1] = (y1 + u1v * Dc1) * (z1 * sigmoidf_(z1));
        }
    }
    #undef NIDX
}

// ---------------- launch ----------------
extern "C" void kernel_launch(void* const* d_in, const int* in_sizes, int n_in,
                              void* d_out, int out_size) {
    const float* x  = (const float*)d_in[0];
    const float* g1 = (const float*)d_in[1];
    const float* b1 = (const float*)d_in[2];
    const float* g2 = (const float*)d_in[3];
    const float* b2 = (const float*)d_in[4];

    int base_f, base_r, base_m;
    if (in_sizes[5] == DM * 2 * DM) {        // merge_W first => dict order
        base_m = 5; base_f = 11; base_r = 20;
    } else {                                  // f_Win first => signature order
        base_f = 5; base_r = 14; base_m = 23;
    }
    const float *Win[2], *convw[2], *convb[2], *Wx[2], *Wdt[2], *bdt[2], *Alog[2], *Dp[2], *Wout[2];
    int bases[2] = {base_f, base_r};
    for (int d = 0; d < 2; d++) {
        int bs = bases[d];
        Win[d]   = (const float*)d_in[bs + 0];
        convw[d] = (const float*)d_in[bs + 1];
        convb[d] = (const float*)d_in[bs + 2];
        Wx[d]    = (const float*)d_in[bs + 3];
        Wdt[d]   = (const float*)d_in[bs + 4];
        bdt[d]   = (const float*)d_in[bs + 5];
        Alog[d]  = (const float*)d_in[bs + 6];
        Dp[d]    = (const float*)d_in[bs + 7];
        Wout[d]  = (const float*)d_in[bs + 8];
    }
    const float* merge_W = (const float*)d_in[base_m + 0];
    const float* merge_b = (const float*)d_in[base_m + 1];
    const float* ffn_W1  = (const float*)d_in[base_m + 2];
    const float* ffn_b1  = (const float*)d_in[base_m + 3];
    const float* ffn_W2  = (const float*)d_in[base_m + 4];
    const float* ffn_b2  = (const float*)d_in[base_m + 5];

    float* ws = nullptr;
    cudaGetSymbolAddress((void**)&ws, g_ws);
    float* xn  = ws + OFF_XN;
    float* xz[2]  = {ws + OFF_XZ0, ws + OFF_XZ1};
    float* u[2]   = {ws + OFF_U0,  ws + OFF_U1};
    float* xd[2]  = {ws + OFF_XD0, ws + OFF_XD1};
    float* dt[2]  = {ws + OFF_DT0, ws + OFF_DT1};
    float* y[2]   = {ws + OFF_Y0,  ws + OFF_Y1};
    float* cat = ws + OFF_CAT;
    float* x1  = ws + OFF_X1;
    float* xn2 = ws + OFF_XN2;
    float* hff = ws + OFF_HFF;

    static int smem_set = 0;
    if (!smem_set) {
        cudaFuncSetAttribute(mm_tf32<0>, cudaFuncAttributeMaxDynamicSharedMemorySize, SMEM_BYTES);
        cudaFuncSetAttribute(mm_tf32<1>, cudaFuncAttributeMaxDynamicSharedMemorySize, SMEM_BYTES);
        cudaFuncSetAttribute(mm_tf32<2>, cudaFuncAttributeMaxDynamicSharedMemorySize, SMEM_BYTES);
        cudaFuncSetAttribute(mm_tf32<3>, cudaFuncAttributeMaxDynamicSharedMemorySize, SMEM_BYTES);
        smem_set = 1;
    }

    const int MTB = MT / 128;  // 18

    ln_kernel<<<MT, 256>>>(x, g1, b1, xn);

    // in-proj for both directions
    {
        PtrSet a{xn, Win[0], nullptr, nullptr, xz[0]};
        PtrSet b{xn, Win[1], nullptr, nullptr, xz[1]};
        mm_tf32<0><<<dim3(MTB, 16, 2), 256, SMEM_BYTES>>>(a, b, DM, 2 * DI, 0, 2 * DI, DM);
    }

    conv_kernel<<<dim3((MT * DI + 255) / 256, 2), 256>>>(
        xz[0], xz[1], convw[0], convw[1], convb[0], convb[1], u[0], u[1]);

    // x-proj (N=64) both dirs
    {
        PtrSet a{u[0], Wx[0], nullptr, nullptr, xd[0]};
        PtrSet b{u[1], Wx[1], nullptr, nullptr, xd[1]};
        mm_tf32<0><<<dim3(MTB, 1, 2), 256, SMEM_BYTES>>>(a, b, DI, 64, 0, 64, DI);
    }

    // dt-proj + softplus, both dirs
    {
        PtrSet a{xd[0], Wdt[0], bdt[0], nullptr, dt[0]};
        PtrSet b{xd[1], Wdt[1], bdt[1], nullptr, dt[1]};
        mm_tf32<1><<<dim3(MTB, 8, 2), 256, SMEM_BYTES>>>(a, b, 64, DI, 0, DI, DTR);
    }

    scan_kernel<<<dim3(BB * (DI / 64), 2), 512>>>(
        u[0], u[1], dt[0], dt[1], xd[0], xd[1], xz[0], xz[1],
        Alog[0], Alog[1], Dp[0], Dp[1], y[0], y[1]);

    // out-proj both dirs -> cat
    {
        PtrSet a{y[0], Wout[0], nullptr, nullptr, cat};
        PtrSet b{y[1], Wout[1], nullptr, nullptr, cat};
        mm_tf32<0><<<dim3(MTB, 4, 2), 256, SMEM_BYTES>>>(a, b, DI, 2 * DM, DM, DM, DI);
    }

    // merge + residual
    {
        PtrSet a{cat, merge_W, merge_b, x, x1};
        mm_tf32<2><<<dim3(MTB, 4, 1), 256, SMEM_BYTES>>>(a, a, 2 * DM, DM, 0, DM, 2 * DM);
    }

    ln_kernel<<<MT, 256>>>(x1, g2, b2, xn2);

    // ffn1 + gelu
    {
        PtrSet a{xn2, ffn_W1, ffn_b1, nullptr, hff};
        mm_tf32<3><<<dim3(MTB, 16, 1), 256, SMEM_BYTES>>>(a, a, DM, 4 * DM, 0, 4 * DM, DM);
    }
    // ffn2 + residual -> out
    {
        PtrSet a{hff, ffn_W2, ffn_b2, x1, (float*)d_out};
        mm_tf32<2><<<dim3(MTB, 4, 1), 256, SMEM_BYTES>>>(a, a, 4 * DM, DM, 0, DM, 4 * DM);
    }
}